// round 3
// baseline (speedup 1.0000x reference)
#include <cuda_runtime.h>
#include <cuda_bf16.h>

// ---------------- problem constants ----------------
#define TT 32
#define BB 32
#define HH 128
#define WW 128
#define CIN 2
#define FH 32
#define FW 32
#define CF 64
#define CP 32
#define OUTD 128
#define PATCH 8
#define PHW 16           // PH = PW = 16
#define NPATCH 256       // PH*PW
#define TOPK_R 4
#define KWTA 16
#define BETA 0.9f
#define VTH 1.0f
#define EVT 0.5f
#define PER 64           // periph spatial = 64x64

// output layout offsets (floats)
#define OFF_OUT 0                         // (32,128) = 4096
#define OFF_LOGITS 4096                   // (32,32,128) = 131072
#define OFF_SR 135168                     // (2,)
#define OFF_ACT 135170                    // scalar
#define OFF_ROUTE 135171                  // (256,)
#define OFF_CHAN 135427                   // (64,)

// ---------------- device scratch ----------------
__device__ float g_vf[BB * CF * FH * FW];          // [b][c][pos] 8 MiB
__device__ float g_vp[BB * CP * PER * PER];        // [b][c][pos] 16 MiB
__device__ float g_ff[BB * CF * FH * FW];          // conv out, same layout
__device__ float g_periph[BB * PER * PER * CIN];   // [b][y][x][c]
__device__ float g_scores[BB * NPATCH];
__device__ float g_sal[BB * CF];
__device__ float g_fused[BB * 96];                 // [0..63]=fovea spike means
__device__ int   g_psum[BB * CP];                  // periph spike counts per (b,c)
__device__ int   g_y0[BB], g_x0[BB];
__device__ int   g_active_acc;
__device__ int   g_sf_acc, g_sp_acc;
__device__ int   g_route_acc[NPATCH];
__device__ int   g_chan_acc[CF];

// ---------------- init ----------------
__global__ void k_init() {
    int i = blockIdx.x * blockDim.x + threadIdx.x;
    int stride = gridDim.x * blockDim.x;
    for (int k = i; k < BB * CF * FH * FW; k += stride) g_vf[k] = 0.f;
    for (int k = i; k < BB * CP * PER * PER; k += stride) g_vp[k] = 0.f;
    if (i < NPATCH) g_route_acc[i] = 0;
    if (i < CF) g_chan_acc[i] = 0;
    if (i == 0) { g_active_acc = 0; g_sf_acc = 0; g_sp_acc = 0; }
}

// periph downsample 1D weights (jax.image.resize linear+antialias, 128->64)
__device__ __forceinline__ void periph_w(int i, int* j, float* w) {
    int j0 = 2 * i - 1;
    if (i == 0)      { w[0] = 0.f;        w[1] = 3.f / 7.f; w[2] = 3.f / 7.f; w[3] = 1.f / 7.f; }
    else if (i == 63){ w[0] = 1.f / 7.f;  w[1] = 3.f / 7.f; w[2] = 3.f / 7.f; w[3] = 0.f; }
    else             { w[0] = 0.125f;     w[1] = 0.375f;    w[2] = 0.375f;    w[3] = 0.125f; }
#pragma unroll
    for (int a = 0; a < 4; a++) { int v = j0 + a; j[a] = v < 0 ? 0 : (v > 127 ? 127 : v); }
}

__device__ __forceinline__ float xs_at(const float* __restrict__ X, int y, int x, int c) {
    float v = X[(y * WW + x) * CIN + c];
    return fabsf(v) > EVT ? v : 0.f;
}

// ---------------- K12: patch scores + active + region topk/argmax + periph downsample ----------------
// one block per batch element
__global__ __launch_bounds__(256) void k12_pre(const float* __restrict__ x_seq, int t) {
    int b = blockIdx.x;
    const float* X = x_seq + ((size_t)t * BB + b) * (HH * WW * CIN);
    int tid = threadIdx.x;

    __shared__ float s[NPATCH];
    __shared__ int acnt[8];
    __shared__ int best;

    // --- phase A: patch score + active count (thread p <-> patch p) ---
    int pr = tid >> 4, pc = tid & 15;
    const float* pp = X + (pr * PATCH * WW + pc * PATCH) * CIN;
    float ssum = 0.f; int cnt = 0;
#pragma unroll
    for (int r = 0; r < PATCH; r++) {
        const float* rp = pp + r * WW * CIN;
#pragma unroll
        for (int q = 0; q < 16; q++) {
            float a = fabsf(rp[q]);
            bool m = a > EVT;
            cnt += m ? 1 : 0;
            ssum += m ? a : 0.f;
        }
    }
    float score = ssum * (1.0f / 128.0f);
    s[tid] = score;
    g_scores[b * NPATCH + tid] = score;
#pragma unroll
    for (int off = 16; off; off >>= 1) cnt += __shfl_down_sync(0xffffffffu, cnt, off);
    if ((tid & 31) == 0) acnt[tid >> 5] = cnt;
    if (tid < CP) g_psum[b * CP + tid] = 0;
    __syncthreads();
    if (tid == 0) {
        int tot = 0;
#pragma unroll
        for (int i = 0; i < 8; i++) tot += acnt[i];
        atomicAdd(&g_active_acc, tot);
    }

    // --- phase B: region top-k gate + first-occurrence argmax -> fovea origin ---
    float v = s[tid];
    int greater = 0, eq_before = 0;
#pragma unroll 8
    for (int q = 0; q < NPATCH; q++) {
        greater += (s[q] > v) ? 1 : 0;
        eq_before += (q < tid && s[q] == v) ? 1 : 0;
    }
    if (greater < TOPK_R) atomicAdd(&g_route_acc[tid], 1);
    if (greater == 0 && eq_before == 0) best = tid;   // exactly one writer (first max)
    __syncthreads();
    if (tid == 0) {
        int py = best >> 4, px = best & 15;
        int cy = py * PATCH + PATCH / 2, cx = px * PATCH + PATCH / 2;
        int y0 = cy - FH / 2; y0 = y0 < 0 ? 0 : (y0 > HH - FH ? HH - FH : y0);
        int x0 = cx - FW / 2; x0 = x0 < 0 ? 0 : (x0 > WW - FW ? WW - FW : x0);
        g_y0[b] = y0; g_x0[b] = x0;
    }

    // --- phase C: periph downsample 128x128 -> 64x64 (separable 4-tap, fused 16 taps) ---
    for (int k = tid; k < PER * PER * CIN; k += 256) {
        int c = k & 1;
        int ox = (k >> 1) & 63;
        int oy = k >> 7;
        int jy[4], jx[4]; float wy[4], wx[4];
        periph_w(oy, jy, wy);
        periph_w(ox, jx, wx);
        float acc = 0.f;
#pragma unroll
        for (int a = 0; a < 4; a++) {
            float ra = 0.f;
#pragma unroll
            for (int bx = 0; bx < 4; bx++) ra += wx[bx] * xs_at(X, jy[a], jx[bx], c);
            acc += wy[a] * ra;
        }
        g_periph[((b * PER + oy) * PER + ox) * CIN + c] = acc;
    }
}

// ---------------- K3: fovea conv (SAME 3x3, cin=2, cout=64) + saliency ----------------
__global__ __launch_bounds__(256) void k3_fovea(const float* __restrict__ x_seq,
                                                const float* __restrict__ w_fovea, int t) {
    int cg = blockIdx.x;   // channel group of 8
    int b = blockIdx.y;
    __shared__ float win[34 * 34 * CIN];
    __shared__ float wk[18 * 8];
    __shared__ float ssal[8];
    const float* X = x_seq + ((size_t)t * BB + b) * (HH * WW * CIN);
    int y0 = g_y0[b], x0 = g_x0[b];
    int tid = threadIdx.x;

    for (int k = tid; k < 34 * 34 * CIN; k += 256) {
        int c = k & 1;
        int sxy = k >> 1;
        int sx = sxy % 34, sy = sxy / 34;
        float v = 0.f;
        if (sy >= 1 && sy <= 32 && sx >= 1 && sx <= 32)
            v = xs_at(X, y0 + sy - 1, x0 + sx - 1, c);
        win[k] = v;
    }
    for (int k = tid; k < 18 * 8; k += 256) {
        int co = k & 7, m = k >> 3;                  // m = (ky*3+kx)*2+ci
        wk[k] = w_fovea[m * CF + cg * 8 + co];
    }
    if (tid < 8) ssal[tid] = 0.f;
    __syncthreads();

    float salacc[8];
#pragma unroll
    for (int i = 0; i < 8; i++) salacc[i] = 0.f;

#pragma unroll
    for (int q = 0; q < 4; q++) {
        int pos = q * 256 + tid;          // 0..1023
        int oy = pos >> 5, ox = pos & 31;
        float in[18];
#pragma unroll
        for (int ky = 0; ky < 3; ky++)
#pragma unroll
            for (int kx = 0; kx < 3; kx++)
#pragma unroll
                for (int ci = 0; ci < 2; ci++)
                    in[(ky * 3 + kx) * 2 + ci] = win[((oy + ky) * 34 + ox + kx) * 2 + ci];
#pragma unroll
        for (int co = 0; co < 8; co++) {
            float acc = 0.f;
#pragma unroll
            for (int m = 0; m < 18; m++) acc += in[m] * wk[m * 8 + co];
            g_ff[((b * CF + cg * 8 + co) << 10) + pos] = acc;
            salacc[co] += fabsf(acc);
        }
    }
#pragma unroll
    for (int co = 0; co < 8; co++) {
        float v = salacc[co];
#pragma unroll
        for (int off = 16; off; off >>= 1) v += __shfl_down_sync(0xffffffffu, v, off);
        if ((tid & 31) == 0) atomicAdd(&ssal[co], v);
    }
    __syncthreads();
    if (tid < 8) g_sal[b * CF + cg * 8 + tid] = ssal[tid];
}

// ---------------- K45: channel k-WTA gate + fovea LIF + spike stats ----------------
__global__ __launch_bounds__(256) void k45_fovea_lif() {
    int bc = blockIdx.x;                 // b*64+c
    int b = bc >> 6, c = bc & 63;
    int tid = threadIdx.x;

    __shared__ float ssal[CF];
    __shared__ int red[8];
    if (tid < CF) ssal[tid] = g_sal[b * CF + tid];
    __syncthreads();

    // gate for this block's channel (saliency sums; mean = sum * 2^-10, order-exact)
    float mysal = ssal[c];
    int greater = 0;
#pragma unroll
    for (int q = 0; q < CF; q++) greater += (ssal[q] > mysal) ? 1 : 0;
    float gate = (greater < KWTA) ? 1.f : 0.f;
    if (tid == 0 && gate > 0.f) atomicAdd(&g_chan_acc[c], 1);

    int base = bc << 10;
    int scount = 0;
#pragma unroll
    for (int q = 0; q < 4; q++) {
        int i = base + q * 256 + tid;
        float v = BETA * g_vf[i] + g_ff[i] * gate;
        float sp = (v - VTH) > 0.f ? 1.f : 0.f;
        v -= sp * VTH;
        g_vf[i] = v;
        scount += (int)sp;
    }
#pragma unroll
    for (int off = 16; off; off >>= 1) scount += __shfl_down_sync(0xffffffffu, scount, off);
    if ((tid & 31) == 0) red[tid >> 5] = scount;
    __syncthreads();
    if (tid == 0) {
        int tot = 0;
#pragma unroll
        for (int i = 0; i < 8; i++) tot += red[i];
        g_fused[b * 96 + c] = (float)tot * (1.f / 1024.f);
        atomicAdd(&g_sf_acc, tot);
    }
}

// ---------------- K6: periph conv (SAME 3x3, cin=2, cout split 16) + LIF fused ----------------
__global__ __launch_bounds__(256) void k6_periph(const float* __restrict__ w_periph) {
    int rchunk = blockIdx.x >> 1;   // 0..7, 8 output rows each
    int g = blockIdx.x & 1;         // cout half: channels g*16..g*16+15
    int b = blockIdx.y;
    __shared__ float win[10 * 66 * CIN];
    __shared__ float wk[18 * 16];
    __shared__ int psum[16];
    __shared__ int ptot;
    int tid = threadIdx.x;

    for (int k = tid; k < 10 * 66 * CIN; k += 256) {
        int c = k & 1;
        int rest = k >> 1;
        int xx = rest % 66, yy = rest / 66;
        int iy = rchunk * 8 + yy - 1, ix = xx - 1;
        float v = 0.f;
        if (iy >= 0 && iy < PER && (unsigned)ix < (unsigned)PER)
            v = g_periph[((b * PER + iy) * PER + ix) * CIN + c];
        win[k] = v;
    }
    for (int k = tid; k < 18 * 16; k += 256) {
        int co = k & 15, m = k >> 4;
        wk[k] = w_periph[m * CP + g * 16 + co];
    }
    if (tid < 16) psum[tid] = 0;
    if (tid == 0) ptot = 0;
    __syncthreads();

    int cnt[16];
#pragma unroll
    for (int i = 0; i < 16; i++) cnt[i] = 0;

#pragma unroll
    for (int q = 0; q < 2; q++) {
        int pos = q * 256 + tid;         // 0..511
        int ry = pos >> 6, x = pos & 63;
        float in[18];
#pragma unroll
        for (int ky = 0; ky < 3; ky++)
#pragma unroll
            for (int kx = 0; kx < 3; kx++)
#pragma unroll
                for (int ci = 0; ci < 2; ci++)
                    in[(ky * 3 + kx) * 2 + ci] = win[((ry + ky) * 66 + x + kx) * 2 + ci];
        int vbase = (b * CP + g * 16) * (PER * PER) + (rchunk * 8 + ry) * PER + x;
#pragma unroll
        for (int co = 0; co < 16; co++) {
            float acc = 0.f;
#pragma unroll
            for (int m = 0; m < 18; m++) acc += in[m] * wk[m * 16 + co];
            int vi = vbase + co * (PER * PER);
            float v = BETA * g_vp[vi] + acc;
            float sp = (v - VTH) > 0.f ? 1.f : 0.f;
            v -= sp * VTH;
            g_vp[vi] = v;
            cnt[co] += (int)sp;
        }
    }
    int tot = 0;
#pragma unroll
    for (int co = 0; co < 16; co++) {
        int c = cnt[co];
#pragma unroll
        for (int off = 16; off; off >>= 1) c += __shfl_down_sync(0xffffffffu, c, off);
        if ((tid & 31) == 0) atomicAdd(&psum[co], c);
        tot += cnt[co];
    }
#pragma unroll
    for (int off = 16; off; off >>= 1) tot += __shfl_down_sync(0xffffffffu, tot, off);
    if ((tid & 31) == 0) atomicAdd(&ptot, tot);
    __syncthreads();
    if (tid < 16) atomicAdd(&g_psum[b * CP + g * 16 + tid], psum[tid]);
    if (tid == 0) atomicAdd(&g_sp_acc, ptot);
}

// ---------------- K7: logits ----------------
__global__ __launch_bounds__(128) void k7_logits(const float* __restrict__ head_w,
                                                 const float* __restrict__ head_b,
                                                 const float* __restrict__ route_w,
                                                 const float* __restrict__ route_b,
                                                 float* __restrict__ out, int t) {
    int b = blockIdx.x, o = threadIdx.x;
    __shared__ float fu[128];
    __shared__ float sc[NPATCH];
    if (o < 64) fu[o] = g_fused[b * 96 + o];
    else if (o < 96) fu[o] = (float)g_psum[b * CP + (o - 64)] * (1.f / 4096.f);
    else fu[o] = 0.f;
    sc[o] = g_scores[b * NPATCH + o];
    sc[o + 128] = g_scores[b * NPATCH + o + 128];
    __syncthreads();
    float acc = head_b[o] + route_b[o];
#pragma unroll 8
    for (int c = 0; c < 96; c++) acc += fu[c] * head_w[c * OUTD + o];
#pragma unroll 8
    for (int p = 0; p < NPATCH; p++) acc += sc[p] * route_w[p * OUTD + o];
    out[OFF_LOGITS + ((size_t)t * BB + b) * OUTD + o] = acc;
}

// ---------------- K8: final reductions ----------------
__global__ __launch_bounds__(256) void k8_final(float* __restrict__ out) {
    if (blockIdx.x < BB) {
        int b = blockIdx.x;
        for (int o = threadIdx.x; o < OUTD; o += 256) {
            float s = 0.f;
            for (int t = 0; t < TT; t++) s += out[OFF_LOGITS + ((size_t)t * BB + b) * OUTD + o];
            out[OFF_OUT + b * OUTD + o] = s * (1.f / (float)TT);
        }
    } else {
        int tid = threadIdx.x;
        if (tid == 0) {
            out[OFF_SR + 0] = (float)g_sf_acc * (1.f / (float)(TT * BB * FH * FW * CF));
            out[OFF_SR + 1] = (float)g_sp_acc * (1.f / (float)((long long)TT * BB * PER * PER * CP));
            out[OFF_ACT] = (float)g_active_acc * (1.f / (float)(TT * BB * HH * WW * CIN));
        }
        if (tid < NPATCH) out[OFF_ROUTE + tid] = (float)g_route_acc[tid] * (1.f / (float)(TT * BB));
        if (tid < CF) out[OFF_CHAN + tid] = (float)g_chan_acc[tid] * (1.f / (float)(TT * BB));
    }
}

// ---------------- launch ----------------
extern "C" void kernel_launch(void* const* d_in, const int* in_sizes, int n_in,
                              void* d_out, int out_size) {
    const float* x_seq   = (const float*)d_in[0];
    const float* w_fovea = (const float*)d_in[1];
    const float* w_periph= (const float*)d_in[2];
    const float* head_w  = (const float*)d_in[3];
    const float* head_b  = (const float*)d_in[4];
    const float* route_w = (const float*)d_in[5];
    const float* route_b = (const float*)d_in[6];
    float* out = (float*)d_out;
    (void)in_sizes; (void)n_in; (void)out_size;

    k_init<<<2048, 256>>>();
    for (int t = 0; t < TT; t++) {
        k12_pre<<<BB, 256>>>(x_seq, t);
        k3_fovea<<<dim3(8, BB), 256>>>(x_seq, w_fovea, t);
        k45_fovea_lif<<<BB * CF, 256>>>();
        k6_periph<<<dim3(16, BB), 256>>>(w_periph);
        k7_logits<<<BB, 128>>>(head_w, head_b, route_w, route_b, out, t);
    }
    k8_final<<<BB + 1, 256>>>(out);
}

// round 15
// speedup vs baseline: 4.2813x; 4.2813x over previous
#include <cuda_runtime.h>
#include <cuda_bf16.h>

// ---------------- problem constants ----------------
#define TT 32
#define BB 32
#define HH 128
#define WW 128
#define CIN 2
#define FH 32
#define FW 32
#define CF 64
#define CP 32
#define OUTD 128
#define PATCH 8
#define PHW 16
#define NPATCH 256
#define TOPK_R 4
#define KWTA 16
#define BETA 0.9f
#define VTH 1.0f
#define EVT 0.5f
#define PER 64

// output layout offsets (floats)
#define OFF_OUT 0
#define OFF_LOGITS 4096
#define OFF_SR 135168
#define OFF_ACT 135170
#define OFF_ROUTE 135171
#define OFF_CHAN 135427

// ---------------- device scratch ----------------
__device__ float g_ff[(size_t)TT * BB * CF * 1024];      // raw fovea conv out, [t][b][c][pos], 256 MiB
__device__ float g_periph[TT * BB * PER * PER * CIN];    // [t][b][y][x][c], 32 MiB
__device__ float g_scores[TT * BB * NPATCH];
__device__ float g_gate[TT * BB * CF];
__device__ int   g_y0[TT * BB], g_x0[TT * BB];
__device__ int   g_fcnt[TT * BB * CF];                   // fovea spike counts per (t,b,c)
__device__ int   g_psum[TT * BB * CP];                   // periph spike counts per (t,b,c)
__device__ int   g_active_acc;
__device__ int   g_route_acc[NPATCH];
__device__ int   g_chan_acc[CF];

// ---------------- f32x2 helpers ----------------
__device__ __forceinline__ unsigned long long pk2(float lo, float hi) {
    unsigned long long r;
    asm("mov.b64 %0, {%1, %2};" : "=l"(r) : "f"(lo), "f"(hi));
    return r;
}
__device__ __forceinline__ void unpk2(unsigned long long v, float& lo, float& hi) {
    asm("mov.b64 {%0, %1}, %2;" : "=f"(lo), "=f"(hi) : "l"(v));
}
__device__ __forceinline__ unsigned long long fma2(unsigned long long a, unsigned long long b,
                                                   unsigned long long c) {
    unsigned long long d;
    asm("fma.rn.f32x2 %0, %1, %2, %3;" : "=l"(d) : "l"(a), "l"(b), "l"(c));
    return d;
}

// ---------------- init: zero accumulators ----------------
__global__ void k_init() {
    int i = blockIdx.x * blockDim.x + threadIdx.x;
    if (i < TT * BB * CP) g_psum[i] = 0;
    if (i < NPATCH) g_route_acc[i] = 0;
    if (i < CF) g_chan_acc[i] = 0;
    if (i == 0) g_active_acc = 0;
}

// periph downsample 1D weights (jax.image.resize linear+antialias, 128->64)
__device__ __forceinline__ void periph_w(int i, int* j, float* w) {
    int j0 = 2 * i - 1;
    if (i == 0)      { w[0] = 0.f;       w[1] = 3.f / 7.f; w[2] = 3.f / 7.f; w[3] = 1.f / 7.f; }
    else if (i == 63){ w[0] = 1.f / 7.f; w[1] = 3.f / 7.f; w[2] = 3.f / 7.f; w[3] = 0.f; }
    else             { w[0] = 0.125f;    w[1] = 0.375f;    w[2] = 0.375f;    w[3] = 0.125f; }
#pragma unroll
    for (int a = 0; a < 4; a++) { int v = j0 + a; j[a] = v < 0 ? 0 : (v > 127 ? 127 : v); }
}

__device__ __forceinline__ float xs_at(const float* __restrict__ X, int y, int x, int c) {
    float v = X[(y * WW + x) * CIN + c];
    return fabsf(v) > EVT ? v : 0.f;
}

// ---------------- kA: per (t,b): scores, active, route gate, argmax, periph resize ----------------
__global__ __launch_bounds__(256) void kA_pre(const float* __restrict__ x_seq) {
    int tb = blockIdx.x;
    const float* X = x_seq + (size_t)tb * (HH * WW * CIN);
    int tid = threadIdx.x;

    __shared__ float s[NPATCH];
    __shared__ int acnt[8];
    __shared__ int best;

    // phase A: patch score (thread == patch) + active count
    int pr = tid >> 4, pc = tid & 15;
    const float* pp = X + (pr * PATCH * WW + pc * PATCH) * CIN;
    float ssum = 0.f; int cnt = 0;
#pragma unroll
    for (int r = 0; r < PATCH; r++) {
        const float* rp = pp + r * WW * CIN;
#pragma unroll
        for (int q = 0; q < 16; q++) {
            float a = fabsf(rp[q]);
            bool m = a > EVT;
            cnt += m ? 1 : 0;
            ssum += m ? a : 0.f;
        }
    }
    float score = ssum * (1.0f / 128.0f);
    s[tid] = score;
    g_scores[tb * NPATCH + tid] = score;
#pragma unroll
    for (int off = 16; off; off >>= 1) cnt += __shfl_down_sync(0xffffffffu, cnt, off);
    if ((tid & 31) == 0) acnt[tid >> 5] = cnt;
    __syncthreads();
    if (tid == 0) {
        int tot = 0;
#pragma unroll
        for (int i = 0; i < 8; i++) tot += acnt[i];
        atomicAdd(&g_active_acc, tot);
    }

    // phase B: top-k route gate + first-occurrence argmax
    float v = s[tid];
    int greater = 0, eq_before = 0;
#pragma unroll 8
    for (int q = 0; q < NPATCH; q++) {
        greater += (s[q] > v) ? 1 : 0;
        eq_before += (q < tid && s[q] == v) ? 1 : 0;
    }
    if (greater < TOPK_R) atomicAdd(&g_route_acc[tid], 1);
    if (greater == 0 && eq_before == 0) best = tid;
    __syncthreads();
    if (tid == 0) {
        int py = best >> 4, px = best & 15;
        int cy = py * PATCH + PATCH / 2, cx = px * PATCH + PATCH / 2;
        int y0 = cy - FH / 2; y0 = y0 < 0 ? 0 : (y0 > HH - FH ? HH - FH : y0);
        int x0 = cx - FW / 2; x0 = x0 < 0 ? 0 : (x0 > WW - FW ? WW - FW : x0);
        g_y0[tb] = y0; g_x0[tb] = x0;
    }

    // phase C: periph downsample 128->64 (separable 4-tap antialiased)
    for (int k = tid; k < PER * PER * CIN; k += 256) {
        int c = k & 1;
        int ox = (k >> 1) & 63;
        int oy = k >> 7;
        int jy[4], jx[4]; float wy[4], wx[4];
        periph_w(oy, jy, wy);
        periph_w(ox, jx, wx);
        float acc = 0.f;
#pragma unroll
        for (int a = 0; a < 4; a++) {
            float ra = 0.f;
#pragma unroll
            for (int bx = 0; bx < 4; bx++) ra += wx[bx] * xs_at(X, jy[a], jx[bx], c);
            acc += wy[a] * ra;
        }
        g_periph[((size_t)tb * PER + oy) * PER * CIN + ox * CIN + c] = acc;
    }
}

// ---------------- kB: fovea conv all (t,b) + saliency + channel gate ----------------
__global__ __launch_bounds__(256) void kB_fovea(const float* __restrict__ x_seq,
                                                const float* __restrict__ w_fovea) {
    int tb = blockIdx.x;
    int tid = threadIdx.x;
    int wid = tid >> 5, lane = tid & 31;
    __shared__ float2 win2[34 * 34];
    __shared__ float wk[18 * 16];
    __shared__ float wsum[8][16];
    __shared__ float s_sal[64];

    const float* X = x_seq + (size_t)tb * (HH * WW * CIN);
    int y0 = g_y0[tb], x0 = g_x0[tb];

    // gather masked fovea window (zero-padded SAME border of the 32x32 crop)
    for (int k = tid; k < 34 * 34; k += 256) {
        int sy = k / 34, sx = k % 34;
        float2 v = make_float2(0.f, 0.f);
        if (sy >= 1 && sy <= 32 && sx >= 1 && sx <= 32) {
            const float* p = X + ((y0 + sy - 1) * WW + (x0 + sx - 1)) * CIN;
            float a0 = p[0], a1 = p[1];
            v.x = fabsf(a0) > EVT ? a0 : 0.f;
            v.y = fabsf(a1) > EVT ? a1 : 0.f;
        }
        win2[k] = v;
    }
    __syncthreads();

    // per-thread input registers for 4 positions
    float in[4][18];
    int posn[4];
#pragma unroll
    for (int p = 0; p < 4; p++) {
        int pos = p * 256 + tid;
        posn[p] = pos;
        int oy = pos >> 5, ox = pos & 31;
#pragma unroll
        for (int ky = 0; ky < 3; ky++)
#pragma unroll
            for (int kx = 0; kx < 3; kx++) {
                float2 v = win2[(oy + ky) * 34 + ox + kx];
                in[p][(ky * 3 + kx) * 2] = v.x;
                in[p][(ky * 3 + kx) * 2 + 1] = v.y;
            }
    }

    for (int g = 0; g < 4; g++) {
        __syncthreads();
        for (int k = tid; k < 288; k += 256) {
            int m = k >> 4, co = k & 15;
            wk[k] = w_fovea[m * CF + g * 16 + co];
        }
        __syncthreads();
#pragma unroll
        for (int co = 0; co < 16; co++) {
            float a0 = 0.f, a1 = 0.f, a2 = 0.f, a3 = 0.f;
#pragma unroll
            for (int m = 0; m < 18; m++) {
                float w = wk[m * 16 + co];
                a0 += in[0][m] * w;
                a1 += in[1][m] * w;
                a2 += in[2][m] * w;
                a3 += in[3][m] * w;
            }
            size_t base = ((size_t)tb * CF + g * 16 + co) << 10;
            g_ff[base + posn[0]] = a0;
            g_ff[base + posn[1]] = a1;
            g_ff[base + posn[2]] = a2;
            g_ff[base + posn[3]] = a3;
            float sal = fabsf(a0) + fabsf(a1) + fabsf(a2) + fabsf(a3);
#pragma unroll
            for (int off = 16; off; off >>= 1) sal += __shfl_down_sync(0xffffffffu, sal, off);
            if (lane == 0) wsum[wid][co] = sal;
        }
        __syncthreads();
        if (tid < 16) {
            float sacc = 0.f;
#pragma unroll
            for (int w = 0; w < 8; w++) sacc += wsum[w][tid];
            s_sal[g * 16 + tid] = sacc;
        }
    }
    __syncthreads();
    if (tid < CF) {
        float v = s_sal[tid];
        int greater = 0;
#pragma unroll
        for (int q = 0; q < CF; q++) greater += (s_sal[q] > v) ? 1 : 0;
        float gate = (greater < KWTA) ? 1.f : 0.f;
        g_gate[tb * CF + tid] = gate;
        if (gate > 0.f) atomicAdd(&g_chan_acc[tid], 1);
    }
}

// ---------------- kD: fovea LIF scan (vf in registers across t; gated ff loads skipped) ----------------
__global__ __launch_bounds__(256) void kD_fovea_lif() {
    int bc = blockIdx.x;                // b*64 + c
    int b = bc >> 6, c = bc & 63;
    int tid = threadIdx.x;
    int wid = tid >> 5, lane = tid & 31;
    __shared__ int wsum[8][TT];

    float vf0 = 0.f, vf1 = 0.f, vf2 = 0.f, vf3 = 0.f;
    for (int t = 0; t < TT; t++) {
        int tb = t * BB + b;
        float gate = g_gate[tb * CF + c];
        float f0 = 0.f, f1 = 0.f, f2 = 0.f, f3 = 0.f;
        if (gate != 0.f) {              // block-uniform branch; gate==0 => ff*0 == 0 exactly
            const float* ffp = g_ff + (((size_t)tb * CF + c) << 10);
            f0 = ffp[tid];
            f1 = ffp[256 + tid];
            f2 = ffp[512 + tid];
            f3 = ffp[768 + tid];
        }
        int cnt = 0;
        float v, sp;
        v = BETA * vf0 + f0; sp = (v - VTH) > 0.f ? 1.f : 0.f; vf0 = v - sp * VTH; cnt += (int)sp;
        v = BETA * vf1 + f1; sp = (v - VTH) > 0.f ? 1.f : 0.f; vf1 = v - sp * VTH; cnt += (int)sp;
        v = BETA * vf2 + f2; sp = (v - VTH) > 0.f ? 1.f : 0.f; vf2 = v - sp * VTH; cnt += (int)sp;
        v = BETA * vf3 + f3; sp = (v - VTH) > 0.f ? 1.f : 0.f; vf3 = v - sp * VTH; cnt += (int)sp;
#pragma unroll
        for (int off = 16; off; off >>= 1) cnt += __shfl_down_sync(0xffffffffu, cnt, off);
        if (lane == 0) wsum[wid][t] = cnt;
    }
    __syncthreads();
    if (tid < TT) {
        int s = 0;
#pragma unroll
        for (int w = 0; w < 8; w++) s += wsum[w][tid];
        g_fcnt[(tid * BB + b) * CF + c] = s;
    }
}

// ---------------- kE: periph conv + LIF fused scan (vp in registers, f32x2 conv) ----------------
__global__ __launch_bounds__(128) void kE_periph(const float* __restrict__ w_periph) {
    int tile = blockIdx.x;              // 0..15 -> 4x4 tiles of 16x16
    int b = blockIdx.y;
    int ty0 = (tile >> 2) * 16, tx0 = (tile & 3) * 16;
    int tid = threadIdx.x;
    int wid = tid >> 5, lane = tid & 31;
    int ty = tid >> 4, tx = tid & 15;   // pos0 (ty,tx), pos1 (ty+8,tx)

    __shared__ float2 tile2[18 * 18];
    __shared__ unsigned long long wkb[18 * CP];   // broadcast-packed (w,w)
    __shared__ int wcnt[4][CP];

    for (int k = tid; k < 18 * CP; k += 128) {
        float w = w_periph[k];          // k = m*32 + co
        wkb[k] = pk2(w, w);
    }
    unsigned long long vp2[CP];
#pragma unroll
    for (int i = 0; i < CP; i++) vp2[i] = 0ULL;
    const unsigned long long beta2 = pk2(BETA, BETA);
    __syncthreads();

    for (int t = 0; t < TT; t++) {
        int tb = t * BB + b;
        const float2* P = (const float2*)g_periph + (size_t)tb * (PER * PER);
        for (int k = tid; k < 18 * 18; k += 128) {
            int sy = k / 18, sx = k % 18;
            int y = ty0 + sy - 1, x = tx0 + sx - 1;
            float2 v = make_float2(0.f, 0.f);
            if ((unsigned)y < (unsigned)PER && (unsigned)x < (unsigned)PER) v = P[y * PER + x];
            tile2[k] = v;
        }
        __syncthreads();

        unsigned long long inpk[18];
#pragma unroll
        for (int ky = 0; ky < 3; ky++)
#pragma unroll
            for (int kx = 0; kx < 3; kx++) {
                float2 a = tile2[(ty + ky) * 18 + tx + kx];
                float2 c2 = tile2[(ty + 8 + ky) * 18 + tx + kx];
                inpk[(ky * 3 + kx) * 2] = pk2(a.x, c2.x);
                inpk[(ky * 3 + kx) * 2 + 1] = pk2(a.y, c2.y);
            }

        unsigned mask0 = 0, mask1 = 0;
#pragma unroll
        for (int co = 0; co < CP; co++) {
            unsigned long long acc = 0ULL;
#pragma unroll
            for (int m = 0; m < 18; m++) acc = fma2(inpk[m], wkb[m * CP + co], acc);
            unsigned long long v2 = fma2(vp2[co], beta2, acc);
            float lo, hi;
            unpk2(v2, lo, hi);
            float sp0 = (lo - VTH) > 0.f ? 1.f : 0.f;
            float sp1 = (hi - VTH) > 0.f ? 1.f : 0.f;
            lo -= sp0 * VTH;
            hi -= sp1 * VTH;
            vp2[co] = pk2(lo, hi);
            mask0 |= (sp0 > 0.f ? 1u : 0u) << co;
            mask1 |= (sp1 > 0.f ? 1u : 0u) << co;
        }

        // deterministic block spike counts via ballots
#pragma unroll
        for (int co = 0; co < CP; co++) {
            unsigned b0 = __ballot_sync(0xffffffffu, (mask0 >> co) & 1u);
            unsigned b1 = __ballot_sync(0xffffffffu, (mask1 >> co) & 1u);
            int cc = __popc(b0) + __popc(b1);
            if (lane == co) wcnt[wid][co] = cc;
        }
        __syncthreads();
        if (wid == 0) {
            int s = wcnt[0][lane] + wcnt[1][lane] + wcnt[2][lane] + wcnt[3][lane];
            atomicAdd(&g_psum[tb * CP + lane], s);
        }
        // next-iteration top sync (after tile load) orders flush vs wcnt rewrite
    }
}

// ---------------- kF: logits for all (t,b) ----------------
__global__ __launch_bounds__(256) void kF_logits(const float* __restrict__ head_w,
                                                 const float* __restrict__ head_b,
                                                 const float* __restrict__ route_w,
                                                 const float* __restrict__ route_b,
                                                 float* __restrict__ out) {
    int t = blockIdx.y;
    int bp = blockIdx.x;                // 0..15 (pairs of b)
    int tid = threadIdx.x;
    int o = tid & 127, bh = tid >> 7;
    int b = bp * 2 + bh;
    int tb = t * BB + b;

    __shared__ float fu[2][96];
    __shared__ float sc[2][NPATCH];
    for (int k = o; k < 96; k += 128)
        fu[bh][k] = (k < 64) ? (float)g_fcnt[tb * CF + k] * (1.f / 1024.f)
                             : (float)g_psum[tb * CP + (k - 64)] * (1.f / 4096.f);
    for (int k = o; k < NPATCH; k += 128) sc[bh][k] = g_scores[tb * NPATCH + k];
    __syncthreads();

    float acc = head_b[o] + route_b[o];
#pragma unroll 8
    for (int c = 0; c < 96; c++) acc += fu[bh][c] * head_w[c * OUTD + o];
#pragma unroll 8
    for (int p = 0; p < NPATCH; p++) acc += sc[bh][p] * route_w[p * OUTD + o];
    out[OFF_LOGITS + (size_t)tb * OUTD + o] = acc;
}

// ---------------- kG: final reductions ----------------
__global__ __launch_bounds__(256) void kG_final(float* __restrict__ out) {
    int tid = threadIdx.x;
    if (blockIdx.x < BB) {
        int b = blockIdx.x;
        if (tid < OUTD) {
            float s = 0.f;
            for (int t = 0; t < TT; t++) s += out[OFF_LOGITS + ((size_t)t * BB + b) * OUTD + tid];
            out[OFF_OUT + b * OUTD + tid] = s * (1.f / (float)TT);
        }
    } else {
        __shared__ int red[8];
        // fovea spike total
        int sf = 0;
        for (int i = tid; i < TT * BB * CF; i += 256) sf += g_fcnt[i];
#pragma unroll
        for (int off = 16; off; off >>= 1) sf += __shfl_down_sync(0xffffffffu, sf, off);
        if ((tid & 31) == 0) red[tid >> 5] = sf;
        __syncthreads();
        if (tid == 0) {
            int tot = 0;
#pragma unroll
            for (int i = 0; i < 8; i++) tot += red[i];
            out[OFF_SR + 0] = (float)tot * (1.f / (float)((long long)TT * BB * FH * FW * CF));
        }
        __syncthreads();
        int sp = 0;
        for (int i = tid; i < TT * BB * CP; i += 256) sp += g_psum[i];
#pragma unroll
        for (int off = 16; off; off >>= 1) sp += __shfl_down_sync(0xffffffffu, sp, off);
        if ((tid & 31) == 0) red[tid >> 5] = sp;
        __syncthreads();
        if (tid == 0) {
            int tot = 0;
#pragma unroll
            for (int i = 0; i < 8; i++) tot += red[i];
            out[OFF_SR + 1] = (float)tot * (1.f / (float)((long long)TT * BB * PER * PER * CP));
            out[OFF_ACT] = (float)g_active_acc * (1.f / (float)((long long)TT * BB * HH * WW * CIN));
        }
        if (tid < NPATCH) out[OFF_ROUTE + tid] = (float)g_route_acc[tid] * (1.f / (float)(TT * BB));
        if (tid < CF) out[OFF_CHAN + tid] = (float)g_chan_acc[tid] * (1.f / (float)(TT * BB));
    }
}

// ---------------- launch ----------------
extern "C" void kernel_launch(void* const* d_in, const int* in_sizes, int n_in,
                              void* d_out, int out_size) {
    const float* x_seq    = (const float*)d_in[0];
    const float* w_fovea  = (const float*)d_in[1];
    const float* w_periph = (const float*)d_in[2];
    const float* head_w   = (const float*)d_in[3];
    const float* head_b   = (const float*)d_in[4];
    const float* route_w  = (const float*)d_in[5];
    const float* route_b  = (const float*)d_in[6];
    float* out = (float*)d_out;
    (void)in_sizes; (void)n_in; (void)out_size;

    k_init<<<128, 256>>>();
    kA_pre<<<TT * BB, 256>>>(x_seq);
    kB_fovea<<<TT * BB, 256>>>(x_seq, w_fovea);
    kE_periph<<<dim3(16, BB), 128>>>(w_periph);
    kD_fovea_lif<<<BB * CF, 256>>>();
    kF_logits<<<dim3(16, TT), 256>>>(head_w, head_b, route_w, route_b, out);
    kG_final<<<BB + 1, 256>>>(out);
}